// round 10
// baseline (speedup 1.0000x reference)
#include <cuda_runtime.h>
#include <cuda_bf16.h>
#include <math.h>
#include <stdint.h>

#define NLAY 6
#define DIM 256
#define VOC 1024
#define SEQ 48
#define BSZ 64
#define LT 49
#define NBD 32         // decoder blocks, 2 batch rows each

__device__ float g_pe[LT * DIM];
__device__ unsigned g_keys[96];
__device__ float g_xA[3072 * DIM];
__device__ float g_xB[3072 * DIM];
__device__ float g_qkvE[3072 * 768];
__device__ float g_oE[3072 * DIM];
__device__ float g_tE[3072 * DIM];
__device__ float g_ffE[3072 * 1024];
__device__ float g_mem[3072 * DIM];
__device__ float g_ckv[NLAY * 3072 * 512];
__device__ float g_skv[(size_t)NLAY * BSZ * LT * 512];

__device__ __forceinline__ float wsum(float s) {
#pragma unroll
    for (int o = 16; o; o >>= 1) s += __shfl_xor_sync(0xffffffffu, s, o);
    return s;
}

__device__ __forceinline__ uint2 tf2x32(unsigned k0, unsigned k1, unsigned x0, unsigned x1) {
    unsigned ks0 = k0, ks1 = k1, ks2 = k0 ^ k1 ^ 0x1BD11BDAu;
    x0 += ks0; x1 += ks1;
#define TFR(r) { x0 += x1; x1 = (x1 << (r)) | (x1 >> (32 - (r))); x1 ^= x0; }
    TFR(13) TFR(15) TFR(26) TFR(6)  x0 += ks1; x1 += ks2 + 1u;
    TFR(17) TFR(29) TFR(16) TFR(24) x0 += ks2; x1 += ks0 + 2u;
    TFR(13) TFR(15) TFR(26) TFR(6)  x0 += ks0; x1 += ks1 + 3u;
    TFR(17) TFR(29) TFR(16) TFR(24) x0 += ks1; x1 += ks2 + 4u;
    TFR(13) TFR(15) TFR(26) TFR(6)  x0 += ks2; x1 += ks0 + 5u;
#undef TFR
    return make_uint2(x0, x1);
}

__device__ __forceinline__ unsigned long long pk2(float x, float y) {
    unsigned long long p;
    asm("mov.b64 %0, {%1, %2};" : "=l"(p) : "f"(x), "f"(y));
    return p;
}
__device__ __forceinline__ void fma2x(unsigned long long& a, unsigned long long x,
                                      unsigned long long y) {
    asm("fma.rn.f32x2 %0, %1, %2, %0;" : "+l"(a) : "l"(x), "l"(y));
}
__device__ __forceinline__ float upsum(unsigned long long a) {
    return __uint_as_float((unsigned)a) + __uint_as_float((unsigned)(a >> 32));
}

// ---------------- setup / encoder kernels ----------------
__global__ void k_pe() {
    int p = blockIdx.x, j = threadIdx.x;
    float dv = expf((float)(2 * j) * (-logf(10000.0f) / 256.0f));
    float a = (float)p * dv;
    g_pe[p * DIM + 2 * j] = sinf(a);
    g_pe[p * DIM + 2 * j + 1] = cosf(a);
}

// jax_threefry_partitionable: split(key,48): subkey[j] = threefry(k1,k2, 0, j)
__global__ void k_keys() {
    int j = threadIdx.x;
    if (j < 48) {
        uint2 r = tf2x32(0u, 42u, 0u, (unsigned)j);
        g_keys[2 * j] = r.x; g_keys[2 * j + 1] = r.y;
    }
}

__global__ void k_embed(const int* __restrict__ xc, const int* __restrict__ xk,
                        const float* __restrict__ emb) {
    int row = blockIdx.x, t = threadIdx.x;
    int b = row / SEQ, s = row % SEQ;
    int idx = (s < 32) ? xc[b * 32 + s] : xk[b * 16 + (s - 32)];
    g_xA[(size_t)row * DIM + t] = emb[((size_t)s * VOC + idx) * DIM + t] + g_pe[s * DIM + t];
}

__global__ void k_gemm(const float* __restrict__ A, const float* __restrict__ W,
                       const float* __restrict__ bias, float* __restrict__ C,
                       int M, int N, int K, int relu) {
    __shared__ float sA[16][65], sB[16][65];
    int m0 = blockIdx.y * 64, n0 = blockIdx.x * 64;
    int tid = threadIdx.x;
    int r = tid >> 2, kk = (tid & 3) * 4;
    int ty = tid >> 4, tx = tid & 15;
    float acc[4][4] = {};
    for (int kb = 0; kb < K; kb += 16) {
        const float* Ap = A + (size_t)(m0 + r) * K + kb + kk;
        const float* Bp = W + (size_t)(n0 + r) * K + kb + kk;
#pragma unroll
        for (int u = 0; u < 4; u++) { sA[kk + u][r] = Ap[u]; sB[kk + u][r] = Bp[u]; }
        __syncthreads();
#pragma unroll
        for (int k = 0; k < 16; k++) {
            float a[4], b[4];
#pragma unroll
            for (int i = 0; i < 4; i++) a[i] = sA[k][ty * 4 + i];
#pragma unroll
            for (int j = 0; j < 4; j++) b[j] = sB[k][tx * 4 + j];
#pragma unroll
            for (int i = 0; i < 4; i++)
#pragma unroll
                for (int j = 0; j < 4; j++) acc[i][j] = fmaf(a[i], b[j], acc[i][j]);
        }
        __syncthreads();
    }
#pragma unroll
    for (int i = 0; i < 4; i++) {
        int m = m0 + ty * 4 + i;
#pragma unroll
        for (int j = 0; j < 4; j++) {
            int n = n0 + tx * 4 + j;
            float c = acc[i][j] + (bias ? bias[n] : 0.f);
            if (relu) c = fmaxf(c, 0.f);
            C[(size_t)m * N + n] = c;
        }
    }
}

__global__ void k_addln(const float* __restrict__ a, const float* __restrict__ b,
                        const float* __restrict__ w, const float* __restrict__ wb,
                        float* __restrict__ out) {
    int row = blockIdx.x, t = threadIdx.x;
    __shared__ float red[16];
    __shared__ float sm, srs;
    float v = a[(size_t)row * DIM + t] + (b ? b[(size_t)row * DIM + t] : 0.f);
    float s = wsum(v), q = wsum(v * v);
    int lane = t & 31, wd = t >> 5;
    if (lane == 0) { red[wd] = s; red[8 + wd] = q; }
    __syncthreads();
    if (t == 0) {
        float S = 0.f, Q = 0.f;
        for (int i = 0; i < 8; i++) { S += red[i]; Q += red[8 + i]; }
        float m = S * (1.f / 256.f);
        sm = m; srs = rsqrtf(Q * (1.f / 256.f) - m * m + 1e-5f);
    }
    __syncthreads();
    out[(size_t)row * DIM + t] = (v - sm) * srs * w[t] + wb[t];
}

__global__ void k_enc_attn(const float* __restrict__ QKV, float* __restrict__ O) {
    int b = blockIdx.x >> 3, h = blockIdx.x & 7, tid = threadIdx.x;
    __shared__ float sQ[48][33], sK[48][33], sV[48][33], sS[48][49];
    for (int i = tid; i < 48 * 32; i += 256) {
        int s = i >> 5, d = i & 31;
        size_t base = (size_t)(b * 48 + s) * 768;
        sQ[s][d] = QKV[base + h * 32 + d];
        sK[s][d] = QKV[base + 256 + h * 32 + d];
        sV[s][d] = QKV[base + 512 + h * 32 + d];
    }
    __syncthreads();
    const float sc = 0.17677669529663687f;
    for (int i = tid; i < 48 * 48; i += 256) {
        int q = i / 48, k = i % 48;
        float s = 0.f;
#pragma unroll
        for (int d = 0; d < 32; d++) s = fmaf(sQ[q][d], sK[k][d], s);
        sS[q][k] = s * sc;
    }
    __syncthreads();
    int lane = tid & 31, wd = tid >> 5;
    for (int q = wd; q < 48; q += 8) {
        float v1 = (lane < 48) ? sS[q][lane] : -1e30f;
        float v2 = (lane + 32 < 48) ? sS[q][lane + 32] : -1e30f;
        float mx = fmaxf(v1, v2);
#pragma unroll
        for (int o = 16; o; o >>= 1) mx = fmaxf(mx, __shfl_xor_sync(0xffffffffu, mx, o));
        float e1 = (lane < 48) ? expf(v1 - mx) : 0.f;
        float e2 = (lane + 32 < 48) ? expf(v2 - mx) : 0.f;
        float inv = 1.f / wsum(e1 + e2);
        if (lane < 48) sS[q][lane] = e1 * inv;
        if (lane + 32 < 48) sS[q][lane + 32] = e2 * inv;
    }
    __syncthreads();
    for (int i = tid; i < 48 * 32; i += 256) {
        int q = i >> 5, d = i & 31;
        float o = 0.f;
#pragma unroll
        for (int k = 0; k < 48; k++) o = fmaf(sS[q][k], sV[k][d], o);
        O[(size_t)(b * 48 + q) * DIM + h * 32 + d] = o;
    }
}

// ---------------- row-local persistent decoder (zero grid barriers) ----------------

// o{0,1}[n] (+)= dot(y{0,1}[0..255], W[n][0..255]) + bias[n]. 16 warps split N.
// Both rows share each W row (read once). f32x2 packed FMA.
__device__ void gemv2c(const float* __restrict__ W, int ldw,
                       const float* __restrict__ bias,
                       const float* __restrict__ y0, const float* __restrict__ y1,
                       float* __restrict__ o0, float* __restrict__ o1,
                       int N, int accum, int relu) {
    int lane = threadIdx.x & 31, wid = threadIdx.x >> 5;
    const float4* y04 = (const float4*)y0;
    const float4* y14 = (const float4*)y1;
    float4 a0 = y04[lane], b0 = y04[lane + 32];
    float4 a1 = y14[lane], b1 = y14[lane + 32];
    unsigned long long yp0[4] = {pk2(a0.x, a0.y), pk2(a0.z, a0.w),
                                 pk2(b0.x, b0.y), pk2(b0.z, b0.w)};
    unsigned long long yp1[4] = {pk2(a1.x, a1.y), pk2(a1.z, a1.w),
                                 pk2(b1.x, b1.y), pk2(b1.z, b1.w)};
#pragma unroll 2
    for (int n = wid; n < N; n += 16) {
        const float4* wr = (const float4*)(W + (size_t)n * ldw);
        float4 wa = wr[lane], wb = wr[lane + 32];
        unsigned long long w0 = pk2(wa.x, wa.y), w1 = pk2(wa.z, wa.w);
        unsigned long long w2 = pk2(wb.x, wb.y), w3 = pk2(wb.z, wb.w);
        unsigned long long ac0 = 0ull, ac1 = 0ull;
        fma2x(ac0, w0, yp0[0]); fma2x(ac1, w0, yp1[0]);
        fma2x(ac0, w1, yp0[1]); fma2x(ac1, w1, yp1[1]);
        fma2x(ac0, w2, yp0[2]); fma2x(ac1, w2, yp1[2]);
        fma2x(ac0, w3, yp0[3]); fma2x(ac1, w3, yp1[3]);
        float s0 = wsum(upsum(ac0));
        float s1 = wsum(upsum(ac1));
        if (lane == 0) {
            float b = bias ? bias[n] : 0.f;
            float v0 = s0 + b, v1 = s1 + b;
            if (accum) { v0 += o0[n]; v1 += o1[n]; }
            if (relu) { v0 = fmaxf(v0, 0.f); v1 = fmaxf(v1, 0.f); }
            o0[n] = v0; o1[n] = v1;
        }
    }
}

// per-row LN over 256 elems, executed by a 256-thread half-block (t = tid&255).
__device__ __forceinline__ float ln2(float v, const float* __restrict__ w,
                                     const float* __restrict__ b,
                                     float* sredr, int t) {
    int lane = t & 31, w8 = t >> 5;
    float s = wsum(v), q = wsum(v * v);
    __syncthreads();
    if (lane == 0) { sredr[w8] = s; sredr[8 + w8] = q; }
    __syncthreads();
    float S = 0.f, Q = 0.f;
#pragma unroll
    for (int i = 0; i < 8; i++) { S += sredr[i]; Q += sredr[8 + i]; }
    float m = S * (1.f / 256.f);
    float rs = rsqrtf(Q * (1.f / 256.f) - m * m + 1e-5f);
    return (v - m) * rs * w[t] + b[t];
}

__global__ void __launch_bounds__(512, 1) k_decoder(
    const float* __restrict__ emb, const float* __restrict__ head_w,
    const float* __restrict__ head_b,
    const float* __restrict__ s_wqkv, const float* __restrict__ s_bqkv,
    const float* __restrict__ s_wo, const float* __restrict__ s_bo,
    const float* __restrict__ c_wqkv, const float* __restrict__ c_bqkv,
    const float* __restrict__ c_wo, const float* __restrict__ c_bo,
    const float* __restrict__ dw1, const float* __restrict__ db1,
    const float* __restrict__ dw2, const float* __restrict__ db2,
    const float* __restrict__ d_lnw, const float* __restrict__ d_lnb,
    const float* __restrict__ lnf_w, const float* __restrict__ lnf_b,
    const float* __restrict__ sos, float* __restrict__ out) {
    __shared__ __align__(16) float sy[2][256];
    __shared__ __align__(16) float sq[2][768];
    __shared__ __align__(16) float sv2[2][256];
    __shared__ __align__(16) float st2[2][256];
    __shared__ __align__(16) float sff[2][1024];
    __shared__ float sp[2][8][64];
    __shared__ float sred[2][16];
    __shared__ float ssv[2][256];
    __shared__ int ssi[2][256];
    __shared__ int sch[2];

    int bi = blockIdx.x, tid = threadIdx.x;
    int lane = tid & 31, wid = tid >> 5;
    int r = tid >> 8, t = tid & 255;     // row-half split
    int r0 = 2 * bi;
    int row = r0 + r;
    const float sc = 0.17677669529663687f;

    sy[r][t] = sos[t] + g_pe[t];
    __syncthreads();

    for (int p = 0; p < SEQ; p++) {
        for (int l = 0; l < NLAY; l++) {
            // ---- self qkv ----
            gemv2c(s_wqkv + (size_t)l * 768 * 256, 256, s_bqkv + l * 768,
                   sy[0], sy[1], sq[0], sq[1], 768, 0, 0);
            __syncthreads();
            // ---- KV append ----
            for (int i = tid; i < 1024; i += 512) {
                int rr = i >> 9, j = i & 511;
                g_skv[((size_t)(l * BSZ + r0 + rr) * LT + p) * 512 + j] = sq[rr][256 + j];
            }
            __syncthreads();
            // ---- self attention: warp = (head, row) ----
            {
                int h = wid & 7, rr = wid >> 3;
                float* cache = g_skv + (size_t)(l * BSZ + r0 + rr) * LT * 512;
                const float* sqh = sq[rr] + h * 32;
                float s1 = -1e30f, s2 = -1e30f;
                if (lane <= p) {
                    const float* kr = cache + (size_t)lane * 512 + h * 32;
                    float s = 0.f;
#pragma unroll
                    for (int d = 0; d < 32; d++) s = fmaf(sqh[d], kr[d], s);
                    s1 = s * sc;
                }
                if (lane + 32 <= p) {
                    const float* kr = cache + (size_t)(lane + 32) * 512 + h * 32;
                    float s = 0.f;
#pragma unroll
                    for (int d = 0; d < 32; d++) s = fmaf(sqh[d], kr[d], s);
                    s2 = s * sc;
                }
                float mx = fmaxf(s1, s2);
#pragma unroll
                for (int o = 16; o; o >>= 1) mx = fmaxf(mx, __shfl_xor_sync(0xffffffffu, mx, o));
                float e1 = (lane <= p) ? expf(s1 - mx) : 0.f;
                float e2 = (lane + 32 <= p) ? expf(s2 - mx) : 0.f;
                float inv = 1.f / wsum(e1 + e2);
                float* spr = sp[rr][h];
                spr[lane] = e1 * inv; spr[lane + 32] = e2 * inv;
                __syncwarp();
                const float* vb = cache + 256 + h * 32 + lane;
                float o0 = 0.f, o1 = 0.f, o2 = 0.f, o3 = 0.f;
                int pe = p + 1, j = 0;
                for (; j + 4 <= pe; j += 4) {
                    o0 = fmaf(spr[j],     vb[(size_t)(j) * 512],     o0);
                    o1 = fmaf(spr[j + 1], vb[(size_t)(j + 1) * 512], o1);
                    o2 = fmaf(spr[j + 2], vb[(size_t)(j + 2) * 512], o2);
                    o3 = fmaf(spr[j + 3], vb[(size_t)(j + 3) * 512], o3);
                }
                for (; j < pe; j++) o0 = fmaf(spr[j], vb[(size_t)j * 512], o0);
                sv2[rr][h * 32 + lane] = (o0 + o1) + (o2 + o3);
            }
            __syncthreads();
            gemv2c(s_wo + (size_t)l * 65536, 256, s_bo + l * 256,
                   sv2[0], sv2[1], st2[0], st2[1], 256, 0, 0);
            __syncthreads();
            {
                float v = sy[r][t] + st2[r][t];
                float yn = ln2(v, d_lnw + (l * 3) * 256, d_lnb + (l * 3) * 256, sred[r], t);
                sy[r][t] = yn;
            }
            __syncthreads();
            // ---- cross attention ----
            gemv2c(c_wqkv + (size_t)l * 768 * 256, 256, c_bqkv + l * 768,
                   sy[0], sy[1], sq[0], sq[1], 256, 0, 0);
            __syncthreads();
            {
                int h = wid & 7, rr = wid >> 3;
                const float* cb = g_ckv + ((size_t)l * 3072 + (size_t)(r0 + rr) * 48) * 512;
                const float* sqh = sq[rr] + h * 32;
                float c1, c2 = -1e30f;
                {
                    const float* kr = cb + (size_t)lane * 512 + h * 32;
                    float s = 0.f;
#pragma unroll
                    for (int d = 0; d < 32; d++) s = fmaf(sqh[d], kr[d], s);
                    c1 = s * sc;
                }
                if (lane < 16) {
                    const float* kr = cb + (size_t)(lane + 32) * 512 + h * 32;
                    float s = 0.f;
#pragma unroll
                    for (int d = 0; d < 32; d++) s = fmaf(sqh[d], kr[d], s);
                    c2 = s * sc;
                }
                float mx = fmaxf(c1, c2);
#pragma unroll
                for (int o = 16; o; o >>= 1) mx = fmaxf(mx, __shfl_xor_sync(0xffffffffu, mx, o));
                float e1 = expf(c1 - mx);
                float e2 = (lane < 16) ? expf(c2 - mx) : 0.f;
                float inv = 1.f / wsum(e1 + e2);
                float* spr = sp[rr][h];
                spr[lane] = e1 * inv;
                if (lane < 16) spr[lane + 32] = e2 * inv;
                __syncwarp();
                const float* vb = cb + 256 + h * 32 + lane;
                float o0 = 0.f, o1 = 0.f, o2 = 0.f, o3 = 0.f;
#pragma unroll 3
                for (int j = 0; j < 48; j += 4) {
                    o0 = fmaf(spr[j],     vb[(size_t)(j) * 512],     o0);
                    o1 = fmaf(spr[j + 1], vb[(size_t)(j + 1) * 512], o1);
                    o2 = fmaf(spr[j + 2], vb[(size_t)(j + 2) * 512], o2);
                    o3 = fmaf(spr[j + 3], vb[(size_t)(j + 3) * 512], o3);
                }
                sv2[rr][h * 32 + lane] = (o0 + o1) + (o2 + o3);
            }
            __syncthreads();
            gemv2c(c_wo + (size_t)l * 65536, 256, c_bo + l * 256,
                   sv2[0], sv2[1], st2[0], st2[1], 256, 0, 0);
            __syncthreads();
            {
                float v = sy[r][t] + st2[r][t];
                float yn = ln2(v, d_lnw + (l * 3 + 1) * 256, d_lnb + (l * 3 + 1) * 256, sred[r], t);
                sy[r][t] = yn;
            }
            __syncthreads();
            // ---- ffn ----
            gemv2c(dw1 + (size_t)l * 1024 * 256, 256, db1 + l * 1024,
                   sy[0], sy[1], sff[0], sff[1], 1024, 0, 1);
            __syncthreads();
            for (int c = 0; c < 4; c++)
                gemv2c(dw2 + (size_t)l * 256 * 1024 + c * 256, 1024,
                       c == 0 ? db2 + l * 256 : (const float*)0,
                       sff[0] + c * 256, sff[1] + c * 256,
                       st2[0], st2[1], 256, c > 0, 0);
            __syncthreads();
            {
                float v = sy[r][t] + st2[r][t];
                float yn = ln2(v, d_lnw + (l * 3 + 2) * 256, d_lnb + (l * 3 + 2) * 256, sred[r], t);
                sy[r][t] = yn;
            }
            __syncthreads();
        }
        // ---- final LN + head ----
        {
            float hv = ln2(sy[r][t], lnf_w + 256, lnf_b + 256, sred[r], t);
            sv2[r][t] = hv;
        }
        __syncthreads();
        float* lg = out + 3072 + (size_t)p * 65536 + (size_t)r0 * 1024;
        gemv2c(head_w + (size_t)p * VOC * 256, 256, head_b + (size_t)p * 1024,
               sv2[0], sv2[1], lg, lg + 1024, 1024, 0, 0);
        __syncthreads();
        // ---- sampling (partitionable threefry + gumbel argmax) ----
        {
            unsigned k0 = g_keys[2 * p], k1 = g_keys[2 * p + 1];
            const float* lgr = lg + r * 1024;
            float best = -1e38f; int bidx = 0;
            for (int v = t; v < 1024; v += 256) {
                unsigned i = (unsigned)(row * 1024 + v);
                uint2 rr2 = tf2x32(k0, k1, 0u, i);
                unsigned bits = rr2.x ^ rr2.y;
                float f = __uint_as_float((bits >> 9) | 0x3f800000u) - 1.0f;
                f = fmaxf(f, 1.17549435e-38f);
                float g = -logf(-logf(f));
                float val = __fdiv_rn(lgr[v], 0.1f) + g;
                if (val > best) { best = val; bidx = v; }
            }
            ssv[r][t] = best; ssi[r][t] = bidx;
            __syncthreads();
            for (int st = 128; st > 0; st >>= 1) {
                if (t < st) {
                    float o = ssv[r][t + st];
                    if (o > ssv[r][t] || (o == ssv[r][t] && ssi[r][t + st] < ssi[r][t])) {
                        ssv[r][t] = o; ssi[r][t] = ssi[r][t + st];
                    }
                }
                __syncthreads();
            }
            if (t == 0) {
                int ch = ssi[r][0];
                sch[r] = ch;
                if (p < 32) out[row * 32 + p] = (float)ch;
                else out[2048 + row * 16 + (p - 32)] = (float)ch;
            }
            __syncthreads();
            if (p < SEQ - 1)
                sy[r][t] = emb[((size_t)p * VOC + sch[r]) * 256 + t] + g_pe[(p + 1) * 256 + t];
            __syncthreads();
        }
    }
}

// ---------------- launcher ----------------
extern "C" void kernel_launch(void* const* d_in, const int* in_sizes, int n_in,
                              void* d_out, int out_size) {
    const int*   x_cont = (const int*)d_in[0];
    const int*   x_cat  = (const int*)d_in[1];
    const float* sos    = (const float*)d_in[2];
    const float* emb    = (const float*)d_in[3];
    const float* head_w = (const float*)d_in[4];
    const float* head_b = (const float*)d_in[5];
    const float* e_wqkv = (const float*)d_in[6];
    const float* e_bqkv = (const float*)d_in[7];
    const float* e_wo   = (const float*)d_in[8];
    const float* e_bo   = (const float*)d_in[9];
    const float* e_w1   = (const float*)d_in[10];
    const float* e_b1   = (const float*)d_in[11];
    const float* e_w2   = (const float*)d_in[12];
    const float* e_b2   = (const float*)d_in[13];
    const float* e_lnw  = (const float*)d_in[14];
    const float* e_lnb  = (const float*)d_in[15];
    const float* s_wqkv = (const float*)d_in[16];
    const float* s_bqkv = (const float*)d_in[17];
    const float* s_wo   = (const float*)d_in[18];
    const float* s_bo   = (const float*)d_in[19];
    const float* c_wqkv = (const float*)d_in[20];
    const float* c_bqkv = (const float*)d_in[21];
    const float* c_wo   = (const float*)d_in[22];
    const float* c_bo   = (const float*)d_in[23];
    const float* dw1    = (const float*)d_in[24];
    const float* db1    = (const float*)d_in[25];
    const float* dw2    = (const float*)d_in[26];
    const float* db2    = (const float*)d_in[27];
    const float* d_lnw  = (const float*)d_in[28];
    const float* d_lnb  = (const float*)d_in[29];
    const float* lnf_w  = (const float*)d_in[30];
    const float* lnf_b  = (const float*)d_in[31];
    float* out = (float*)d_out;

#define SYM(p, s) float* p; cudaGetSymbolAddress((void**)&p, s)
    SYM(xA, g_xA); SYM(xB, g_xB); SYM(qkvE, g_qkvE); SYM(oE, g_oE); SYM(tE, g_tE);
    SYM(ffE, g_ffE); SYM(mem, g_mem); SYM(ckv, g_ckv);
#undef SYM

    auto gemm = [&](const float* A, const float* W, const float* B, float* C,
                    int M, int N, int K, int relu) {
        k_gemm<<<dim3(N / 64, M / 64), 256>>>(A, W, B, C, M, N, K, relu);
    };

    k_pe<<<49, 128>>>();
    k_keys<<<1, 64>>>();
    k_embed<<<3072, 256>>>(x_cont, x_cat, emb);

    for (int l = 0; l < NLAY; l++) {
        gemm(xA, e_wqkv + (size_t)l * 768 * 256, e_bqkv + l * 768, qkvE, 3072, 768, 256, 0);
        k_enc_attn<<<512, 256>>>(qkvE, oE);
        gemm(oE, e_wo + (size_t)l * 65536, e_bo + l * 256, tE, 3072, 256, 256, 0);
        k_addln<<<3072, 256>>>(xA, tE, e_lnw + (l * 2) * 256, e_lnb + (l * 2) * 256, xB);
        gemm(xB, e_w1 + (size_t)l * 1024 * 256, e_b1 + l * 1024, ffE, 3072, 1024, 256, 1);
        gemm(ffE, e_w2 + (size_t)l * 256 * 1024, e_b2 + l * 256, tE, 3072, 256, 1024, 0);
        k_addln<<<3072, 256>>>(xB, tE, e_lnw + (l * 2 + 1) * 256, e_lnb + (l * 2 + 1) * 256, xA);
    }
    k_addln<<<3072, 256>>>(xA, nullptr, lnf_w, lnf_b, mem);
    for (int l = 0; l < NLAY; l++)
        gemm(mem, c_wqkv + (size_t)l * 768 * 256 + 256 * 256, c_bqkv + l * 768 + 256,
             ckv + (size_t)l * 3072 * 512, 3072, 512, 256, 0);

    k_decoder<<<NBD, 512>>>(emb, head_w, head_b,
                            s_wqkv, s_bqkv, s_wo, s_bo,
                            c_wqkv, c_bqkv, c_wo, c_bo,
                            dw1, db1, dw2, db2,
                            d_lnw, d_lnb, lnf_w, lnf_b, sos, out);
}